// round 1
// baseline (speedup 1.0000x reference)
#include <cuda_runtime.h>

#define TT 64
#define BB 256
#define DD 512

// Scratch: pre-activations pre[row][gate][q], row = t*BB + b   (1.57 MB)
__device__ __align__(16) float g_pre[TT * BB * 24];

// ---------------------------------------------------------------------------
// K1: pre[t,b,g,q] = inputs[t,b,:] @ Wg[:512,q] + bg[q] + theta_g[q]
// grid 128 blocks x 256 threads; block handles 128 rows.
// warp w: gate = w&3, row-half = w>>2; each lane owns 2 adjacent rows.
// ---------------------------------------------------------------------------
__global__ void __launch_bounds__(256, 1) k1_gemm(
    const float* __restrict__ X,
    const float* __restrict__ Wf, const float* __restrict__ bf,
    const float* __restrict__ Wi, const float* __restrict__ bi,
    const float* __restrict__ Wu, const float* __restrict__ bu,
    const float* __restrict__ Wo, const float* __restrict__ bo,
    const float* __restrict__ thf, const float* __restrict__ thi,
    const float* __restrict__ thu, const float* __restrict__ tho)
{
    __shared__ float Wph[256 * 24];   // K-half of W, [dd][g*6+q]        24576 B
    __shared__ float Xsh[32 * 130];   // x tile transposed [d][row], pad 16640 B

    const int tid  = threadIdx.x;
    const int warp = tid >> 5;
    const int lane = tid & 31;
    const int gate = warp & 3;
    const int rloc = ((warp >> 2) << 6) + (lane << 1);   // block-local row (even)
    const int rowbase = blockIdx.x << 7;

    const float* bg = (gate == 0) ? bf  : (gate == 1) ? bi  : (gate == 2) ? bu  : bo;
    const float* tg = (gate == 0) ? thf : (gate == 1) ? thi : (gate == 2) ? thu : tho;

    float acc0[6], acc1[6];
#pragma unroll
    for (int q = 0; q < 6; q++) {
        float bias = __ldg(bg + q) + __ldg(tg + q);   // fold theta into bias
        acc0[q] = bias;
        acc1[q] = bias;
    }

    const int cc = tid & 7;   // d-group for staging
    const int rr = tid >> 3;  // row for staging

    for (int kh = 0; kh < 2; kh++) {
        __syncthreads();  // prior compute done before Wph overwrite
        // load W half (rows kh*256 .. kh*256+255) into shared, all 4 gates
#pragma unroll
        for (int k = 0; k < 24; k++) {
            int idx = tid + (k << 8);          // 0..6143 == dd*24 + col
            int dd  = idx / 24;
            int col = idx - dd * 24;
            int g2  = col / 6;
            int q2  = col - g2 * 6;
            const float* Ws = (g2 == 0) ? Wf : (g2 == 1) ? Wi : (g2 == 2) ? Wu : Wo;
            Wph[idx] = Ws[((kh << 8) + dd) * 6 + q2];
        }
        for (int tile = 0; tile < 8; tile++) {
            const int d0 = (kh << 8) + (tile << 5);
            __syncthreads();  // Wph visible (tile 0); Xsh free to overwrite
            // stage 128 rows x 32 d, transposed into Xsh[d][row]
#pragma unroll
            for (int p = 0; p < 4; p++) {
                int r = rr + (p << 5);
                const float4 v = *reinterpret_cast<const float4*>(
                    X + (size_t)(rowbase + r) * DD + d0 + (cc << 2));
                Xsh[((cc << 2) + 0) * 130 + r] = v.x;
                Xsh[((cc << 2) + 1) * 130 + r] = v.y;
                Xsh[((cc << 2) + 2) * 130 + r] = v.z;
                Xsh[((cc << 2) + 3) * 130 + r] = v.w;
            }
            __syncthreads();
#pragma unroll
            for (int d = 0; d < 32; d++) {
                const int dd = (tile << 5) + d;
                const float2 w01 = *reinterpret_cast<const float2*>(&Wph[dd * 24 + gate * 6 + 0]);
                const float2 w23 = *reinterpret_cast<const float2*>(&Wph[dd * 24 + gate * 6 + 2]);
                const float2 w45 = *reinterpret_cast<const float2*>(&Wph[dd * 24 + gate * 6 + 4]);
                const float2 x2  = *reinterpret_cast<const float2*>(&Xsh[d * 130 + rloc]);
                acc0[0] = fmaf(x2.x, w01.x, acc0[0]);
                acc0[1] = fmaf(x2.x, w01.y, acc0[1]);
                acc0[2] = fmaf(x2.x, w23.x, acc0[2]);
                acc0[3] = fmaf(x2.x, w23.y, acc0[3]);
                acc0[4] = fmaf(x2.x, w45.x, acc0[4]);
                acc0[5] = fmaf(x2.x, w45.y, acc0[5]);
                acc1[0] = fmaf(x2.y, w01.x, acc1[0]);
                acc1[1] = fmaf(x2.y, w01.y, acc1[1]);
                acc1[2] = fmaf(x2.y, w23.x, acc1[2]);
                acc1[3] = fmaf(x2.y, w23.y, acc1[3]);
                acc1[4] = fmaf(x2.y, w45.x, acc1[4]);
                acc1[5] = fmaf(x2.y, w45.y, acc1[5]);
            }
        }
    }

    float* dst = g_pre + (size_t)(rowbase + rloc) * 24 + gate * 6;
    *reinterpret_cast<float2*>(dst + 0)      = make_float2(acc0[0], acc0[1]);
    *reinterpret_cast<float2*>(dst + 2)      = make_float2(acc0[2], acc0[3]);
    *reinterpret_cast<float2*>(dst + 4)      = make_float2(acc0[4], acc0[5]);
    *reinterpret_cast<float2*>(dst + 24 + 0) = make_float2(acc1[0], acc1[1]);
    *reinterpret_cast<float2*>(dst + 24 + 2) = make_float2(acc1[2], acc1[3]);
    *reinterpret_cast<float2*>(dst + 24 + 4) = make_float2(acc1[4], acc1[5]);
}

// ---------------------------------------------------------------------------
// K2: LSTM scan over T. grid 32 blocks x 32 threads (1 warp).
// lane = (batch-in-block<<2) | gate ; h,c replicated across the 4 gate lanes.
// qlayer(a)[0] = z1 z2 z3 z4 z5 ; qlayer(a)[k] = z0..zk, z = cos(a).
// ---------------------------------------------------------------------------
__global__ void __launch_bounds__(32, 1) k2_scan(
    const float* __restrict__ Wf, const float* __restrict__ Wi,
    const float* __restrict__ Wu, const float* __restrict__ Wo,
    float* __restrict__ out)
{
    const int lane = threadIdx.x;
    const int g    = lane & 3;
    const int b    = (blockIdx.x << 3) + (lane >> 2);
    const float* Wg = (g == 0) ? Wf : (g == 1) ? Wi : (g == 2) ? Wu : Wo;

    // recurrent weights Wh[j][q] = Wg[512+j][q], kept in registers
    float Wh[36];
#pragma unroll
    for (int j = 0; j < 6; j++)
#pragma unroll
        for (int q = 0; q < 6; q++)
            Wh[j * 6 + q] = __ldg(Wg + (DD + j) * 6 + q);

    float h[6], c[6];
#pragma unroll
    for (int q = 0; q < 6; q++) { h[q] = 0.0f; c[q] = 0.0f; }

    const float* pbase = g_pre + (size_t)b * 24 + g * 6;
    float p[6];
    {
        float2 t0 = *reinterpret_cast<const float2*>(pbase + 0);
        float2 t1 = *reinterpret_cast<const float2*>(pbase + 2);
        float2 t2 = *reinterpret_cast<const float2*>(pbase + 4);
        p[0] = t0.x; p[1] = t0.y; p[2] = t1.x; p[3] = t1.y; p[4] = t2.x; p[5] = t2.y;
    }

    const unsigned mask = 0xffffffffu;
    const int qb = lane & ~3;
    const bool isU = (g == 2);

    for (int t = 0; t < TT; t++) {
        // prefetch next step's pre (hides L2 latency behind this step's math)
        const int tn = (t < TT - 1) ? t + 1 : t;
        const float* pnp = pbase + (size_t)tn * (BB * 24);
        const float2 n0 = *reinterpret_cast<const float2*>(pnp + 0);
        const float2 n1 = *reinterpret_cast<const float2*>(pnp + 2);
        const float2 n2 = *reinterpret_cast<const float2*>(pnp + 4);

        // a[q] = pre + h @ Wh   (bias+theta already folded into pre)
        float a[6];
#pragma unroll
        for (int q = 0; q < 6; q++) a[q] = p[q];
#pragma unroll
        for (int j = 0; j < 6; j++)
#pragma unroll
            for (int q = 0; q < 6; q++)
                a[q] = fmaf(h[j], Wh[j * 6 + q], a[q]);

        float z[6];
#pragma unroll
        for (int q = 0; q < 6; q++) z[q] = __cosf(a[q]);

        // entanglement products
        float w[6];
        w[1] = z[0] * z[1];
        w[2] = w[1] * z[2];
        w[3] = w[2] * z[3];
        w[4] = w[3] * z[4];
        w[5] = w[4] * z[5];
        w[0] = (z[1] * z[2]) * (z[3] * z[4]) * z[5];

        // activation: sigmoid for f,i,o ; tanh(x) = 2*sigmoid(2x)-1 for u
        float v[6];
#pragma unroll
        for (int q = 0; q < 6; q++) {
            float xa = isU ? 2.0f * w[q] : w[q];
            float e  = __expf(-xa);
            float s  = __fdividef(1.0f, 1.0f + e);
            v[q] = isU ? fmaf(2.0f, s, -1.0f) : s;
        }

        // gather the 4 gates' values for this batch and update (replicated)
#pragma unroll
        for (int q = 0; q < 6; q++) {
            float fq = __shfl_sync(mask, v[q], qb + 0);
            float iq = __shfl_sync(mask, v[q], qb + 1);
            float uq = __shfl_sync(mask, v[q], qb + 2);
            float oq = __shfl_sync(mask, v[q], qb + 3);
            float cn = fmaf(fq, c[q], iq * uq);
            c[q] = cn;
            float e2 = __expf(2.0f * cn);
            float th = 1.0f - __fdividef(2.0f, e2 + 1.0f);   // tanh(cn)
            h[q] = oq * th;
        }

        if (g == 0) {
            float* o0 = out + ((size_t)t * BB + b) * 6;
            *reinterpret_cast<float2*>(o0 + 0) = make_float2(h[0], h[1]);
            *reinterpret_cast<float2*>(o0 + 2) = make_float2(h[2], h[3]);
            *reinterpret_cast<float2*>(o0 + 4) = make_float2(h[4], h[5]);
        }

        p[0] = n0.x; p[1] = n0.y; p[2] = n1.x; p[3] = n1.y; p[4] = n2.x; p[5] = n2.y;
    }

    if (g == 0) {
        float* hx = out + (size_t)TT * BB * 6 + (size_t)b * 6;
        float* cx = hx + BB * 6;
        *reinterpret_cast<float2*>(hx + 0) = make_float2(h[0], h[1]);
        *reinterpret_cast<float2*>(hx + 2) = make_float2(h[2], h[3]);
        *reinterpret_cast<float2*>(hx + 4) = make_float2(h[4], h[5]);
        *reinterpret_cast<float2*>(cx + 0) = make_float2(c[0], c[1]);
        *reinterpret_cast<float2*>(cx + 2) = make_float2(c[2], c[3]);
        *reinterpret_cast<float2*>(cx + 4) = make_float2(c[4], c[5]);
    }
}

extern "C" void kernel_launch(void* const* d_in, const int* in_sizes, int n_in,
                              void* d_out, int out_size)
{
    const float* X   = (const float*)d_in[0];
    const float* Wf  = (const float*)d_in[1];
    const float* bf  = (const float*)d_in[2];
    const float* Wi  = (const float*)d_in[3];
    const float* bi  = (const float*)d_in[4];
    const float* Wu  = (const float*)d_in[5];
    const float* bu  = (const float*)d_in[6];
    const float* Wo  = (const float*)d_in[7];
    const float* bo  = (const float*)d_in[8];
    const float* thf = (const float*)d_in[9];
    const float* thi = (const float*)d_in[10];
    const float* thu = (const float*)d_in[11];
    const float* tho = (const float*)d_in[12];
    float* out = (float*)d_out;

    k1_gemm<<<128, 256>>>(X, Wf, bf, Wi, bi, Wu, bu, Wo, bo, thf, thi, thu, tho);
    k2_scan<<<32, 32>>>(Wf, Wi, Wu, Wo, out);
}

// round 2
// speedup vs baseline: 1.2816x; 1.2816x over previous
#include <cuda_runtime.h>

#define TT 64
#define BB 256
#define DD 512

// pre-activations, K2-block-contiguous layout:
// g_pre2[bblk(32)][t(64)][bloc(8)][gate(4)][q(6)]
__device__ __align__(16) float g_pre2[TT * BB * 24];

// ---------------------------------------------------------------------------
// K1: pre[t,b,g,q] = inputs[t,b,:] @ Wg[:512,q] + bg[q] + theta_g[q]
// grid 128 x 256 threads; block = 128 rows of one t.
// warp w: gate = w&3, row-half = w>>2; lane owns 2 adjacent rows.
// Inner product uses packed fma.rn.f32x2 (FFMA2): acc pairs (q0,q1),(q2,q3),(q4,q5).
// ---------------------------------------------------------------------------
__global__ void __launch_bounds__(256, 1) k1_gemm(
    const float* __restrict__ X,
    const float* __restrict__ Wf, const float* __restrict__ bf,
    const float* __restrict__ Wi, const float* __restrict__ bi,
    const float* __restrict__ Wu, const float* __restrict__ bu,
    const float* __restrict__ Wo, const float* __restrict__ bo,
    const float* __restrict__ thf, const float* __restrict__ thi,
    const float* __restrict__ thu, const float* __restrict__ tho)
{
    __shared__ float Wph[256 * 24];   // K-half of W, [dd][g*6+q]
    __shared__ float Xsh[32 * 130];   // x tile transposed [d][row], pad (130 even)

    const int tid  = threadIdx.x;
    const int warp = tid >> 5;
    const int lane = tid & 31;
    const int gate = warp & 3;
    const int rloc = ((warp >> 2) << 6) + (lane << 1);   // block-local row (even)
    const int rowbase = blockIdx.x << 7;

    const float* bg = (gate == 0) ? bf  : (gate == 1) ? bi  : (gate == 2) ? bu  : bo;
    const float* tg = (gate == 0) ? thf : (gate == 1) ? thi : (gate == 2) ? thu : tho;

    // packed accumulators: (q0,q1) (q2,q3) (q4,q5) for each of 2 rows
    unsigned long long a0[3], a1[3];
#pragma unroll
    for (int p = 0; p < 3; p++) {
        float blo = __ldg(bg + 2 * p + 0) + __ldg(tg + 2 * p + 0);
        float bhi = __ldg(bg + 2 * p + 1) + __ldg(tg + 2 * p + 1);
        unsigned long long bp;
        asm("mov.b64 %0, {%1, %2};" : "=l"(bp) : "f"(blo), "f"(bhi));
        a0[p] = bp;
        a1[p] = bp;
    }

    const int cc = tid & 7;   // d-group for staging
    const int rr = tid >> 3;  // row for staging

    for (int kh = 0; kh < 2; kh++) {
        __syncthreads();  // prior compute done before Wph overwrite
#pragma unroll
        for (int k = 0; k < 24; k++) {
            int idx = tid + (k << 8);          // dd*24 + col
            int dd  = idx / 24;
            int col = idx - dd * 24;
            int g2  = col / 6;
            int q2  = col - g2 * 6;
            const float* Ws = (g2 == 0) ? Wf : (g2 == 1) ? Wi : (g2 == 2) ? Wu : Wo;
            Wph[idx] = Ws[((kh << 8) + dd) * 6 + q2];
        }
        for (int tile = 0; tile < 8; tile++) {
            const int d0 = (kh << 8) + (tile << 5);
            __syncthreads();
#pragma unroll
            for (int p = 0; p < 4; p++) {
                int r = rr + (p << 5);
                const float4 v = *reinterpret_cast<const float4*>(
                    X + (size_t)(rowbase + r) * DD + d0 + (cc << 2));
                Xsh[((cc << 2) + 0) * 130 + r] = v.x;
                Xsh[((cc << 2) + 1) * 130 + r] = v.y;
                Xsh[((cc << 2) + 2) * 130 + r] = v.z;
                Xsh[((cc << 2) + 3) * 130 + r] = v.w;
            }
            __syncthreads();
#pragma unroll
            for (int d = 0; d < 32; d++) {
                const int dd = (tile << 5) + d;
                const unsigned long long* wp =
                    reinterpret_cast<const unsigned long long*>(&Wph[dd * 24 + gate * 6]);
                const unsigned long long w01 = wp[0];
                const unsigned long long w23 = wp[1];
                const unsigned long long w45 = wp[2];
                const float2 x2 = *reinterpret_cast<const float2*>(&Xsh[d * 130 + rloc]);
                unsigned long long xr0, xr1;
                asm("mov.b64 %0, {%1, %1};" : "=l"(xr0) : "f"(x2.x));
                asm("mov.b64 %0, {%1, %1};" : "=l"(xr1) : "f"(x2.y));
                asm("fma.rn.f32x2 %0, %1, %2, %0;" : "+l"(a0[0]) : "l"(w01), "l"(xr0));
                asm("fma.rn.f32x2 %0, %1, %2, %0;" : "+l"(a0[1]) : "l"(w23), "l"(xr0));
                asm("fma.rn.f32x2 %0, %1, %2, %0;" : "+l"(a0[2]) : "l"(w45), "l"(xr0));
                asm("fma.rn.f32x2 %0, %1, %2, %0;" : "+l"(a1[0]) : "l"(w01), "l"(xr1));
                asm("fma.rn.f32x2 %0, %1, %2, %0;" : "+l"(a1[1]) : "l"(w23), "l"(xr1));
                asm("fma.rn.f32x2 %0, %1, %2, %0;" : "+l"(a1[2]) : "l"(w45), "l"(xr1));
            }
        }
    }

    // row = t*BB + b ; store to block-contiguous layout
    const int t = rowbase >> 8;
    const int b = (rowbase & 255) + rloc;       // even; b+1 shares b>>3
    float* dst = g_pre2 + ((size_t)((b >> 3) * 64 + t) * 192) + (b & 7) * 24 + gate * 6;
    unsigned long long* d64 = reinterpret_cast<unsigned long long*>(dst);
    d64[0] = a0[0]; d64[1] = a0[1]; d64[2] = a0[2];
    unsigned long long* e64 = reinterpret_cast<unsigned long long*>(dst + 24);
    e64[0] = a1[0]; e64[1] = a1[1]; e64[2] = a1[2];
}

// ---------------------------------------------------------------------------
// K2: LSTM scan. grid 32 x 128. All 4 warps stage this block's 48KB of pre
// into SMEM; warp 0 scans. lane = (batch-in-block<<2) | gate.
// qlayer(a)[0] = z1..z5 ; qlayer(a)[k] = z0..zk, z = cos(a).
// ---------------------------------------------------------------------------
__global__ void __launch_bounds__(128, 1) k2_scan(
    const float* __restrict__ Wf, const float* __restrict__ Wi,
    const float* __restrict__ Wu, const float* __restrict__ Wo,
    float* __restrict__ out)
{
    __shared__ float ps[TT * 192];    // 49152 B : [t][bloc][gate][q]

    const int tid = threadIdx.x;

    // cooperative bulk load (coalesced float4)
    {
        const float4* src = reinterpret_cast<const float4*>(g_pre2 + (size_t)blockIdx.x * (TT * 192));
        float4* dst = reinterpret_cast<float4*>(ps);
#pragma unroll
        for (int i = 0; i < (TT * 192) / 4 / 128; i++)
            dst[tid + i * 128] = src[tid + i * 128];
    }
    __syncthreads();
    if (tid >= 32) return;

    const int lane = tid;
    const int g    = lane & 3;
    const int bl   = lane >> 2;
    const int b    = (blockIdx.x << 3) + bl;
    const float* Wg = (g == 0) ? Wf : (g == 1) ? Wi : (g == 2) ? Wu : Wo;

    float Wh[36];
#pragma unroll
    for (int j = 0; j < 6; j++)
#pragma unroll
        for (int q = 0; q < 6; q++)
            Wh[j * 6 + q] = __ldg(Wg + (DD + j) * 6 + q);

    float h[6], c[6];
#pragma unroll
    for (int q = 0; q < 6; q++) { h[q] = 0.0f; c[q] = 0.0f; }

    const float* pb = ps + bl * 24 + g * 6;
    const unsigned mask = 0xffffffffu;
    const int qb = lane & ~3;
    const bool isU = (g == 2);
    const float sgn = isU ? 2.0f : 1.0f;   // exp argument scale

#pragma unroll 2
    for (int t = 0; t < TT; t++) {
        const float2 p0 = *reinterpret_cast<const float2*>(pb + t * 192 + 0);
        const float2 p1 = *reinterpret_cast<const float2*>(pb + t * 192 + 2);
        const float2 p2 = *reinterpret_cast<const float2*>(pb + t * 192 + 4);
        float p[6] = { p0.x, p0.y, p1.x, p1.y, p2.x, p2.y };

        // a[q] = p[q] + h @ Wh  -- two parallel partials, then add (shorter chain)
        float a[6];
#pragma unroll
        for (int q = 0; q < 6; q++) {
            float u0 = fmaf(h[0], Wh[0 * 6 + q], fmaf(h[1], Wh[1 * 6 + q], fmaf(h[2], Wh[2 * 6 + q], p[q])));
            float u1 = fmaf(h[3], Wh[3 * 6 + q], fmaf(h[4], Wh[4 * 6 + q], h[5] * Wh[5 * 6 + q]));
            a[q] = u0 + u1;
        }

        float z[6];
#pragma unroll
        for (int q = 0; q < 6; q++) z[q] = __cosf(a[q]);

        // prefix products (tree form)
        float z01 = z[0] * z[1];
        float z23 = z[2] * z[3];
        float z45 = z[4] * z[5];
        float w[6];
        w[1] = z01;
        w[2] = z01 * z[2];
        w[3] = z01 * z23;
        w[4] = w[3] * z[4];
        w[5] = w[3] * z45;
        w[0] = z[1] * (z23 * z45);

        // f,i,o: sigmoid(w) ; u: tanh(w) = 2*sigmoid(2w)-1
        float v[6];
#pragma unroll
        for (int q = 0; q < 6; q++) {
            float e  = __expf(-sgn * w[q]);
            float s  = __fdividef(1.0f, 1.0f + e);
            v[q] = isU ? fmaf(2.0f, s, -1.0f) : s;
        }

#pragma unroll
        for (int q = 0; q < 6; q++) {
            float fq = __shfl_sync(mask, v[q], qb + 0);
            float iq = __shfl_sync(mask, v[q], qb + 1);
            float uq = __shfl_sync(mask, v[q], qb + 2);
            float oq = __shfl_sync(mask, v[q], qb + 3);
            float cn = fmaf(fq, c[q], iq * uq);
            c[q] = cn;
            float e2 = __expf(2.0f * cn);
            float th = 1.0f - __fdividef(2.0f, e2 + 1.0f);   // tanh(cn)
            h[q] = oq * th;
        }

        if (g == 0) {
            float* o0 = out + ((size_t)t * BB + b) * 6;
            *reinterpret_cast<float2*>(o0 + 0) = make_float2(h[0], h[1]);
            *reinterpret_cast<float2*>(o0 + 2) = make_float2(h[2], h[3]);
            *reinterpret_cast<float2*>(o0 + 4) = make_float2(h[4], h[5]);
        }
    }

    if (g == 0) {
        float* hx = out + (size_t)TT * BB * 6 + (size_t)b * 6;
        float* cx = hx + BB * 6;
        *reinterpret_cast<float2*>(hx + 0) = make_float2(h[0], h[1]);
        *reinterpret_cast<float2*>(hx + 2) = make_float2(h[2], h[3]);
        *reinterpret_cast<float2*>(hx + 4) = make_float2(h[4], h[5]);
        *reinterpret_cast<float2*>(cx + 0) = make_float2(c[0], c[1]);
        *reinterpret_cast<float2*>(cx + 2) = make_float2(c[2], c[3]);
        *reinterpret_cast<float2*>(cx + 4) = make_float2(c[4], c[5]);
    }
}

extern "C" void kernel_launch(void* const* d_in, const int* in_sizes, int n_in,
                              void* d_out, int out_size)
{
    const float* X   = (const float*)d_in[0];
    const float* Wf  = (const float*)d_in[1];
    const float* bf  = (const float*)d_in[2];
    const float* Wi  = (const float*)d_in[3];
    const float* bi  = (const float*)d_in[4];
    const float* Wu  = (const float*)d_in[5];
    const float* bu  = (const float*)d_in[6];
    const float* Wo  = (const float*)d_in[7];
    const float* bo  = (const float*)d_in[8];
    const float* thf = (const float*)d_in[9];
    const float* thi = (const float*)d_in[10];
    const float* thu = (const float*)d_in[11];
    const float* tho = (const float*)d_in[12];
    float* out = (float*)d_out;

    k1_gemm<<<128, 256>>>(X, Wf, bf, Wi, bi, Wu, bu, Wo, bo, thf, thi, thu, tho);
    k2_scan<<<32, 128>>>(Wf, Wi, Wu, Wo, out);
}